// round 1
// baseline (speedup 1.0000x reference)
#include <cuda_runtime.h>
#include <cstdint>

#define NMAX 50000
#define H 128
#define DIN 256
#define KTOT 256
#define TPB 256
#define ROWS_TILE 128
#define APAD 132

// Scratch (device globals: no allocations allowed)
__device__ float g_h0[NMAX * H];
__device__ float g_h1[NMAX * H];
__device__ float g_agg[NMAX * H];
__device__ int   g_cnt[NMAX];

// ---------------------------------------------------------------------------
// Zero scratch: agg (n*H floats) and optionally cnt
__global__ void zero_kernel(int n4agg, int n4cnt) {
    int idx = blockIdx.x * blockDim.x + threadIdx.x;
    if (idx < n4agg) ((float4*)g_agg)[idx] = make_float4(0.f, 0.f, 0.f, 0.f);
    if (idx < n4cnt) ((int4*)g_cnt)[idx] = make_int4(0, 0, 0, 0);
}

// ---------------------------------------------------------------------------
// Scatter: agg[dst] += h[src]  (one warp per edge, float4 per lane)
// SRC: 0 -> g_h0, 1 -> g_h1
template<int SRC, bool DO_CNT>
__global__ void scatter_kernel(const int* __restrict__ ei, int E) {
    int idx = blockIdx.x * blockDim.x + threadIdx.x;
    int total = E * 32;
    if (idx >= total) return;
    int e    = idx >> 5;
    int part = idx & 31;
    int s = __ldg(ei + e);
    int d = __ldg(ei + E + e);
    const float* h = (SRC == 0) ? g_h0 : g_h1;
    float4 v = __ldg((const float4*)(h + (size_t)s * H) + part);
    float4* ap = ((float4*)(g_agg + (size_t)d * H)) + part;
    asm volatile("red.global.add.v4.f32 [%0], {%1,%2,%3,%4};"
                 :: "l"(ap), "f"(v.x), "f"(v.y), "f"(v.z), "f"(v.w)
                 : "memory");
    if (DO_CNT && part == 0) atomicAdd(g_cnt + d, 1);
}

// ---------------------------------------------------------------------------
// Unified fused GEMM: out[N,128] = Acat[N,256] @ Wcat[256,128] + epilogue
// MODE 0: A = x, W = W_in, epi = +b_in +kind_embed[kind] +relay*ext_seed -> g_h0
// MODE 1: A = [agg/cnt | g_h0], W = [Wl1;Wr1], epi = +bl1, LayerNorm, relu -> g_h1
// MODE 2: A = [agg/cnt | g_h1], W = [Wl2;Wr2], epi = +bl2 -> outExt
template<int MODE>
__global__ void __launch_bounds__(TPB, 1)
fused_gemm(const float* __restrict__ Aext,   // MODE0: x
           const float* __restrict__ W0,     // W_in or Wl
           const float* __restrict__ W1,     // Wr (unused MODE0)
           const float* __restrict__ bias,
           const float* __restrict__ aux0,   // MODE0: kind_embed; MODE1: gamma
           const float* __restrict__ aux1,   // MODE0: ext_seed;  MODE1: beta
           const int*   __restrict__ node_kind,
           float* __restrict__ outExt,       // MODE2 output
           int n)
{
    extern __shared__ float sm[];
    float* Wsh   = sm;                     // KTOT*H      = 32768
    float* Ash   = Wsh + KTOT * H;         // 32*APAD     = 4224
    float* bsh   = Ash + 32 * APAD;        // 128
    float* esh   = bsh + H;                // 512
    float* invsh = esh + 512;              // 128

    int tid = threadIdx.x;
    int tc = tid & 15;        // col group 0..15
    int tr = tid >> 4;        // row group 0..15

    // Stage weights (concat for MODE 1/2)
    for (int i = tid; i < (KTOT * H) / 4; i += TPB) {
        float4 v;
        if (MODE == 0) {
            v = __ldg((const float4*)W0 + i);
        } else {
            const int half = (H * H) / 4;
            v = (i < half) ? __ldg((const float4*)W0 + i)
                           : __ldg((const float4*)W1 + (i - half));
        }
        ((float4*)Wsh)[i] = v;
    }
    if (tid < H) bsh[tid] = __ldg(bias + tid);
    if (MODE == 0) {
        for (int i = tid; i < 3 * H; i += TPB) esh[i] = __ldg(aux0 + i);
        if (tid < H) esh[3 * H + tid] = __ldg(aux1 + tid);
    } else if (MODE == 1) {
        if (tid < H) { esh[tid] = __ldg(aux0 + tid); esh[H + tid] = __ldg(aux1 + tid); }
    }

    const float* A = (MODE == 0) ? Aext : (MODE == 1 ? (const float*)g_h0 : (const float*)g_h1);

    int ntiles = (n + ROWS_TILE - 1) / ROWS_TILE;
    for (int tile = blockIdx.x; tile < ntiles; tile += gridDim.x) {
        int row0 = tile * ROWS_TILE;
        __syncthreads();
        if (MODE != 0) {
            if (tid < ROWS_TILE) {
                int r = row0 + tid;
                int c = (r < n) ? g_cnt[r] : 1;
                if (c < 1) c = 1;
                invsh[tid] = 1.0f / (float)c;
            }
        }

        float acc[8][8];
        #pragma unroll
        for (int i = 0; i < 8; i++)
            #pragma unroll
            for (int j = 0; j < 8; j++) acc[i][j] = 0.f;

        for (int kc = 0; kc < KTOT; kc += 32) {
            __syncthreads();
            // Stage 128 rows x 32 k, transposed (k-major) into Ash
            #pragma unroll
            for (int it = 0; it < 4; it++) {
                int t  = tid + it * TPB;   // 0..1023
                int r  = t >> 3;           // 0..127
                int kk = (t & 7) * 4;      // 0,4,..,28
                int row = row0 + r;
                float4 v = make_float4(0.f, 0.f, 0.f, 0.f);
                if (row < n) {
                    if (MODE == 0) {
                        v = __ldg((const float4*)(A + (size_t)row * DIN + kc + kk));
                    } else {
                        if (kc < H) {
                            v = __ldg((const float4*)(g_agg + (size_t)row * H + kc + kk));
                            float iv = invsh[r];
                            v.x *= iv; v.y *= iv; v.z *= iv; v.w *= iv;
                        } else {
                            v = __ldg((const float4*)(A + (size_t)row * H + (kc - H) + kk));
                        }
                    }
                }
                Ash[(kk + 0) * APAD + r] = v.x;
                Ash[(kk + 1) * APAD + r] = v.y;
                Ash[(kk + 2) * APAD + r] = v.z;
                Ash[(kk + 3) * APAD + r] = v.w;
            }
            __syncthreads();

            #pragma unroll 8
            for (int kk = 0; kk < 32; kk++) {
                float4 a0 = *(const float4*)&Ash[kk * APAD + tr * 8];
                float4 a1 = *(const float4*)&Ash[kk * APAD + tr * 8 + 4];
                float4 b0 = *(const float4*)&Wsh[(kc + kk) * H + tc * 8];
                float4 b1 = *(const float4*)&Wsh[(kc + kk) * H + tc * 8 + 4];
                float a[8] = {a0.x, a0.y, a0.z, a0.w, a1.x, a1.y, a1.z, a1.w};
                float b[8] = {b0.x, b0.y, b0.z, b0.w, b1.x, b1.y, b1.z, b1.w};
                #pragma unroll
                for (int i = 0; i < 8; i++)
                    #pragma unroll
                    for (int j = 0; j < 8; j++)
                        acc[i][j] += a[i] * b[j];
            }
        }

        // Epilogue
        int colb = tc * 8;
        if (MODE == 0) {
            #pragma unroll
            for (int i = 0; i < 8; i++) {
                int row = row0 + tr * 8 + i;
                if (row < n) {
                    int kind = __ldg(node_kind + row);
                    const float* emb = esh + kind * H;
                    bool relay = (kind != 0);
                    float o[8];
                    #pragma unroll
                    for (int j = 0; j < 8; j++) {
                        int c = colb + j;
                        float v = acc[i][j] + bsh[c] + emb[c];
                        if (relay) v += esh[3 * H + c];
                        o[j] = v;
                    }
                    float4* op = (float4*)(g_h0 + (size_t)row * H + colb);
                    op[0] = make_float4(o[0], o[1], o[2], o[3]);
                    op[1] = make_float4(o[4], o[5], o[6], o[7]);
                }
            }
        } else if (MODE == 1) {
            #pragma unroll
            for (int i = 0; i < 8; i++) {
                int row = row0 + tr * 8 + i;
                float vv[8];
                float rs = 0.f, rss = 0.f;
                #pragma unroll
                for (int j = 0; j < 8; j++) {
                    float v = acc[i][j] + bsh[colb + j];
                    vv[j] = v; rs += v; rss += v * v;
                }
                // reduce across the 16 lanes (same tr) holding this row
                #pragma unroll
                for (int m = 8; m >= 1; m >>= 1) {
                    rs  += __shfl_xor_sync(0xffffffffu, rs,  m);
                    rss += __shfl_xor_sync(0xffffffffu, rss, m);
                }
                float mu   = rs * (1.0f / H);
                float var  = rss * (1.0f / H) - mu * mu;
                float rstd = rsqrtf(var + 1e-5f);
                if (row < n) {
                    float o[8];
                    #pragma unroll
                    for (int j = 0; j < 8; j++) {
                        int c = colb + j;
                        float v = (vv[j] - mu) * rstd * esh[c] + esh[H + c];
                        o[j] = fmaxf(v, 0.f);
                    }
                    float4* op = (float4*)(g_h1 + (size_t)row * H + colb);
                    op[0] = make_float4(o[0], o[1], o[2], o[3]);
                    op[1] = make_float4(o[4], o[5], o[6], o[7]);
                }
            }
        } else {
            #pragma unroll
            for (int i = 0; i < 8; i++) {
                int row = row0 + tr * 8 + i;
                if (row < n) {
                    float o[8];
                    #pragma unroll
                    for (int j = 0; j < 8; j++) o[j] = acc[i][j] + bsh[colb + j];
                    float4* op = (float4*)(outExt + (size_t)row * H + colb);
                    op[0] = make_float4(o[0], o[1], o[2], o[3]);
                    op[1] = make_float4(o[4], o[5], o[6], o[7]);
                }
            }
        }
    }
}

// ---------------------------------------------------------------------------
extern "C" void kernel_launch(void* const* d_in, const int* in_sizes, int n_in,
                              void* d_out, int out_size) {
    const float* x          = (const float*)d_in[0];
    const int*   ei         = (const int*)d_in[1];
    const int*   node_kind  = (const int*)d_in[2];
    const float* W_in       = (const float*)d_in[3];
    const float* b_in       = (const float*)d_in[4];
    const float* kind_embed = (const float*)d_in[5];
    const float* ext_seed   = (const float*)d_in[6];
    const float* Wl1        = (const float*)d_in[7];
    const float* bl1        = (const float*)d_in[8];
    const float* Wr1        = (const float*)d_in[9];
    const float* gamma      = (const float*)d_in[10];
    const float* beta       = (const float*)d_in[11];
    const float* Wl2        = (const float*)d_in[12];
    const float* bl2        = (const float*)d_in[13];
    const float* Wr2        = (const float*)d_in[14];

    int n = in_sizes[2];          // N (node_kind count)
    int E = in_sizes[1] / 2;      // edges

    const size_t smem = (size_t)(KTOT * H + 32 * APAD + H + 512 + H) * sizeof(float);
    cudaFuncSetAttribute(fused_gemm<0>, cudaFuncAttributeMaxDynamicSharedMemorySize, (int)smem);
    cudaFuncSetAttribute(fused_gemm<1>, cudaFuncAttributeMaxDynamicSharedMemorySize, (int)smem);
    cudaFuncSetAttribute(fused_gemm<2>, cudaFuncAttributeMaxDynamicSharedMemorySize, (int)smem);

    int ntiles = (n + ROWS_TILE - 1) / ROWS_TILE;

    int n4agg = (n * H) / 4;
    int n4cnt = (n + 3) / 4;
    int zgrid = (n4agg + 255) / 256;

    int sthreads = E * 32;
    int sgrid = (sthreads + 255) / 256;

    // Pipeline (single stream, serialized):
    zero_kernel<<<zgrid, 256>>>(n4agg, n4cnt);
    fused_gemm<0><<<ntiles, TPB, smem>>>(x, W_in, nullptr, b_in, kind_embed,
                                         ext_seed, node_kind, nullptr, n);
    scatter_kernel<0, true><<<sgrid, 256>>>(ei, E);
    fused_gemm<1><<<ntiles, TPB, smem>>>(nullptr, Wl1, Wr1, bl1, gamma, beta,
                                         nullptr, nullptr, n);
    zero_kernel<<<zgrid, 256>>>(n4agg, 0);
    scatter_kernel<1, false><<<sgrid, 256>>>(ei, E);
    fused_gemm<2><<<ntiles, TPB, smem>>>(nullptr, Wl2, Wr2, bl2, nullptr, nullptr,
                                         nullptr, (float*)d_out, n);
}

// round 3
// speedup vs baseline: 1.0677x; 1.0677x over previous
#include <cuda_runtime.h>
#include <cstdint>

#define NMAX 50000
#define H 128
#define KTOT 256
#define TPB 256
#define ROWS_TILE 128
#define WSTR 136   // Wsh float stride (128+8): conflict-free b-frag loads
#define ASTR 36    // Ash float stride (32+4): conflict-free a-frag loads

// -------------------- scratch (no allocations allowed) ----------------------
__device__ float g_h0[NMAX * H];
__device__ float g_h1[NMAX * H];
__device__ float g_agg[NMAX * H];
__device__ int   g_cnt[NMAX];

// -------------------- helpers ------------------------------------------------
__device__ __forceinline__ uint32_t tf32r(float x) {
    uint32_t r; asm("cvt.rna.tf32.f32 %0, %1;" : "=r"(r) : "f"(x));
    return r;
}
__device__ __forceinline__ void mma_tf32(float* d, const uint32_t* a, const uint32_t* b) {
    asm volatile("mma.sync.aligned.m16n8k8.row.col.f32.tf32.tf32.f32 "
                 "{%0,%1,%2,%3}, {%4,%5,%6,%7}, {%8,%9}, {%0,%1,%2,%3};"
                 : "+f"(d[0]), "+f"(d[1]), "+f"(d[2]), "+f"(d[3])
                 : "r"(a[0]), "r"(a[1]), "r"(a[2]), "r"(a[3]),
                   "r"(b[0]), "r"(b[1]));
}

// -------------------- zero + scatter -----------------------------------------
__global__ void zero_kernel(int n4agg, int n4cnt) {
    int idx = blockIdx.x * blockDim.x + threadIdx.x;
    if (idx < n4agg) ((float4*)g_agg)[idx] = make_float4(0.f, 0.f, 0.f, 0.f);
    if (idx < n4cnt) ((int4*)g_cnt)[idx] = make_int4(0, 0, 0, 0);
}

template<int SRC, bool DO_CNT>
__global__ void scatter_kernel(const int* __restrict__ ei, int E) {
    int idx = blockIdx.x * blockDim.x + threadIdx.x;
    int total = E * 32;
    if (idx >= total) return;
    int e    = idx >> 5;
    int part = idx & 31;
    int s = __ldg(ei + e);
    int d = __ldg(ei + E + e);
    const float* h = (SRC == 0) ? g_h0 : g_h1;
    float4 v = __ldg((const float4*)(h + (size_t)s * H) + part);
    float4* ap = ((float4*)(g_agg + (size_t)d * H)) + part;
    asm volatile("red.global.add.v4.f32 [%0], {%1,%2,%3,%4};"
                 :: "l"(ap), "f"(v.x), "f"(v.y), "f"(v.z), "f"(v.w)
                 : "memory");
    if (DO_CNT && part == 0) atomicAdd(g_cnt + d, 1);
}

// smem layout (floats)
#define SMF_W     0                         // 256*136 = 34816
#define SMF_A     (SMF_W + KTOT * WSTR)     // 128*36 = 4608
#define SMF_C     (SMF_A + 128 * ASTR)      // 768 consts
#define SMF_RS    (SMF_C + 768)             // 128*4
#define SMF_RSS   (SMF_RS + 512)            // 128*4
#define SMF_MU    (SMF_RSS + 512)           // 128
#define SMF_RSTD  (SMF_MU + 128)            // 128
#define SMF_INV   (SMF_RSTD + 128)          // 128
#define SMF_KIND  (SMF_INV + 128)           // 128 (as int)
#define SMF_TOTAL (SMF_KIND + 128)
#define SM_BYTES  (SMF_TOTAL * 4)

// -------------------- tf32 mma GEMM + fused epilogue -------------------------
// MODE 0: A=x[N,256], W=W_in           -> h0 = ..+b_in+kind_embed[k]+relay*ext
// MODE 1: A=[agg/cnt | h0], W=[Wl1;Wr1]-> relu(LN(..+bl1)) -> h1
// MODE 2: A=[agg/cnt | h1], W=[Wl2;Wr2]-> ..+bl2 -> out
template<int MODE>
__global__ void __launch_bounds__(TPB, 1)
tc_gemm(const float* __restrict__ Aext,
        const float* __restrict__ W0,
        const float* __restrict__ W1,
        const float* __restrict__ bias,
        const float* __restrict__ aux0,   // MODE0 kind_embed / MODE1 gamma
        const float* __restrict__ aux1,   // MODE0 ext_seed   / MODE1 beta
        const int*   __restrict__ node_kind,
        float* __restrict__ outExt,
        int n)
{
    extern __shared__ float sm[];
    float* Wsh   = sm + SMF_W;
    float* Ash   = sm + SMF_A;
    float* csh   = sm + SMF_C;
    float* rs    = sm + SMF_RS;
    float* rss   = sm + SMF_RSS;
    float* mus   = sm + SMF_MU;
    float* rstds = sm + SMF_RSTD;
    float* invsh = sm + SMF_INV;
    int*   kindsh = (int*)(sm + SMF_KIND);

    const int tid = threadIdx.x;
    const int wid = tid >> 5;
    const int lid = tid & 31;
    const int lq = lid >> 2;      // lane/4
    const int lr = lid & 3;       // lane%4
    const int wr = wid & 1;       // warp row   (0..1) -> 64 rows
    const int cw = wid >> 1;      // warp col   (0..3) -> 32 cols
    const int colb0 = cw * 32;

    // ---- stage consts ----
    if (tid < H) csh[tid] = __ldg(bias + tid);
    if (MODE == 0) {
        for (int i = tid; i < 3 * H; i += TPB) csh[H + i] = __ldg(aux0 + i);
        if (tid < H) csh[4 * H + tid] = __ldg(aux1 + tid);
    } else if (MODE == 1) {
        if (tid < H) { csh[H + tid] = __ldg(aux0 + tid); csh[2 * H + tid] = __ldg(aux1 + tid); }
    }

    // ---- stage W [K=256][N=128] tf32, stride WSTR (once per CTA) ----
    for (int i = tid; i < KTOT * (H / 4); i += TPB) {   // 8192 float4s
        int k  = i >> 5;
        int nq = i & 31;
        float4 v;
        if (MODE == 0) v = __ldg((const float4*)W0 + i);
        else           v = (k < H) ? __ldg((const float4*)W0 + i)
                                   : __ldg((const float4*)W1 + (i - H * (H / 4)));
        uint4 t;
        t.x = tf32r(v.x); t.y = tf32r(v.y); t.z = tf32r(v.z); t.w = tf32r(v.w);
        *(uint4*)&Wsh[k * WSTR + nq * 4] = t;
    }

    const float* Asrc = (MODE == 1) ? (const float*)g_h0 : (const float*)g_h1;
    int ntiles = (n + ROWS_TILE - 1) >> 7;

    for (int tile = blockIdx.x; tile < ntiles; tile += gridDim.x) {
        int row0 = tile << 7;
        __syncthreads();   // prior tile fully retired before touching per-tile smem

        if (MODE != 0 && tid < ROWS_TILE) {
            int r = row0 + tid;
            int c = (r < n) ? g_cnt[r] : 1;
            if (c < 1) c = 1;
            invsh[tid] = 1.0f / (float)c;
        }
        if (MODE == 0 && tid < ROWS_TILE) {
            int r = row0 + tid;
            kindsh[tid] = (r < n) ? __ldg(node_kind + r) : 0;
        }

        float acc[4][4][4];
        #pragma unroll
        for (int mf = 0; mf < 4; mf++)
            #pragma unroll
            for (int nf = 0; nf < 4; nf++)
                #pragma unroll
                for (int q = 0; q < 4; q++) acc[mf][nf][q] = 0.f;

        for (int kc = 0; kc < KTOT; kc += 32) {
            __syncthreads();
            // stage A chunk: 128 rows x 32 k, tf32, stride ASTR
            #pragma unroll
            for (int it = 0; it < 4; it++) {
                int i   = tid + it * TPB;
                int row = i >> 3;
                int kq  = i & 7;
                int gr  = row0 + row;
                float4 v = make_float4(0.f, 0.f, 0.f, 0.f);
                if (gr < n) {
                    if (MODE == 0) {
                        v = __ldg((const float4*)(Aext + (size_t)gr * KTOT + kc) + kq);
                    } else if (kc < H) {
                        v = __ldg((const float4*)(g_agg + (size_t)gr * H + kc) + kq);
                        float iv = invsh[row];
                        v.x *= iv; v.y *= iv; v.z *= iv; v.w *= iv;
                    } else {
                        v = __ldg((const float4*)(Asrc + (size_t)gr * H + (kc - H)) + kq);
                    }
                }
                uint4 t;
                t.x = tf32r(v.x); t.y = tf32r(v.y); t.z = tf32r(v.z); t.w = tf32r(v.w);
                *(uint4*)&Ash[row * ASTR + kq * 4] = t;
            }
            __syncthreads();

            #pragma unroll
            for (int ks = 0; ks < 4; ks++) {
                uint32_t a[4][4];
                #pragma unroll
                for (int mf = 0; mf < 4; mf++) {
                    const uint32_t* ap =
                        (const uint32_t*)&Ash[(wr * 64 + mf * 16 + lq) * ASTR + ks * 8 + lr];
                    a[mf][0] = ap[0];
                    a[mf][1] = ap[8 * ASTR];
                    a[mf][2] = ap[4];
                    a[mf][3] = ap[8 * ASTR + 4];
                }
                uint32_t b[4][2];
                #pragma unroll
                for (int nf = 0; nf < 4; nf++) {
                    const uint32_t* bp =
                        (const uint32_t*)&Wsh[(kc + ks * 8 + lr) * WSTR + colb0 + nf * 8 + lq];
                    b[nf][0] = bp[0];
                    b[nf][1] = bp[4 * WSTR];
                }
                #pragma unroll
                for (int mf = 0; mf < 4; mf++)
                    #pragma unroll
                    for (int nf = 0; nf < 4; nf++)
                        mma_tf32(acc[mf][nf], a[mf], b[nf]);
            }
        }

        // ---------------- epilogue ----------------
        // thread owns: rows (wr*64 + mf*16 + lq) and (+8); cols colb0+nf*8+2*lr+{0,1}
        // add bias in-place
        #pragma unroll
        for (int mf = 0; mf < 4; mf++)
            #pragma unroll
            for (int nf = 0; nf < 4; nf++) {
                int c0 = colb0 + nf * 8 + 2 * lr;
                float b0v = csh[c0], b1v = csh[c0 + 1];
                acc[mf][nf][0] += b0v; acc[mf][nf][1] += b1v;
                acc[mf][nf][2] += b0v; acc[mf][nf][3] += b1v;
            }

        if (MODE == 1) {
            // partial row sums across this warp's 32 cols
            #pragma unroll
            for (int mf = 0; mf < 4; mf++) {
                float slo = 0.f, sslo = 0.f, shi = 0.f, sshi = 0.f;
                #pragma unroll
                for (int nf = 0; nf < 4; nf++) {
                    float v0 = acc[mf][nf][0], v1 = acc[mf][nf][1];
                    float v2 = acc[mf][nf][2], v3 = acc[mf][nf][3];
                    slo += v0 + v1;  sslo += v0 * v0 + v1 * v1;
                    shi += v2 + v3;  sshi += v2 * v2 + v3 * v3;
                }
                #pragma unroll
                for (int m = 1; m <= 2; m <<= 1) {
                    slo  += __shfl_xor_sync(0xffffffffu, slo,  m);
                    sslo += __shfl_xor_sync(0xffffffffu, sslo, m);
                    shi  += __shfl_xor_sync(0xffffffffu, shi,  m);
                    sshi += __shfl_xor_sync(0xffffffffu, sshi, m);
                }
                if (lr == 0) {
                    int rlo = wr * 64 + mf * 16 + lq;
                    rs [rlo * 4 + cw] = slo;  rss[rlo * 4 + cw] = sslo;
                    rs [(rlo + 8) * 4 + cw] = shi;  rss[(rlo + 8) * 4 + cw] = sshi;
                }
            }
            __syncthreads();
            if (tid < 128) {
                float s  = rs [tid * 4] + rs [tid * 4 + 1] + rs [tid * 4 + 2] + rs [tid * 4 + 3];
                float ss = rss[tid * 4] + rss[tid * 4 + 1] + rss[tid * 4 + 2] + rss[tid * 4 + 3];
                float mu  = s * (1.0f / H);
                float var = ss * (1.0f / H) - mu * mu;
                mus[tid] = mu;
                rstds[tid] = rsqrtf(var + 1e-5f);
            }
            __syncthreads();
            #pragma unroll
            for (int mf = 0; mf < 4; mf++) {
                int lrow = wr * 64 + mf * 16 + lq;
                float mu_lo = mus[lrow],     rd_lo = rstds[lrow];
                float mu_hi = mus[lrow + 8], rd_hi = rstds[lrow + 8];
                int glo = row0 + lrow, ghi = glo + 8;
                #pragma unroll
                for (int nf = 0; nf < 4; nf++) {
                    int c0 = colb0 + nf * 8 + 2 * lr;
                    float g0 = csh[H + c0], g1 = csh[H + c0 + 1];
                    float be0 = csh[2 * H + c0], be1 = csh[2 * H + c0 + 1];
                    if (glo < n) {
                        float2 o;
                        o.x = fmaxf((acc[mf][nf][0] - mu_lo) * rd_lo * g0 + be0, 0.f);
                        o.y = fmaxf((acc[mf][nf][1] - mu_lo) * rd_lo * g1 + be1, 0.f);
                        *(float2*)(g_h1 + (size_t)glo * H + c0) = o;
                    }
                    if (ghi < n) {
                        float2 o;
                        o.x = fmaxf((acc[mf][nf][2] - mu_hi) * rd_hi * g0 + be0, 0.f);
                        o.y = fmaxf((acc[mf][nf][3] - mu_hi) * rd_hi * g1 + be1, 0.f);
                        *(float2*)(g_h1 + (size_t)ghi * H + c0) = o;
                    }
                }
            }
        } else {
            #pragma unroll
            for (int mf = 0; mf < 4; mf++) {
                int lrow = wr * 64 + mf * 16 + lq;
                int glo = row0 + lrow, ghi = glo + 8;
                int klo = 0, khi = 0;
                bool rlo = false, rhi = false;
                if (MODE == 0) {
                    klo = kindsh[lrow]; khi = kindsh[lrow + 8];
                    rlo = (klo != 0);   rhi = (khi != 0);
                }
                float* dst = (MODE == 0) ? g_h0 : outExt;
                #pragma unroll
                for (int nf = 0; nf < 4; nf++) {
                    int c0 = colb0 + nf * 8 + 2 * lr;
                    if (glo < n) {
                        float2 o = make_float2(acc[mf][nf][0], acc[mf][nf][1]);
                        if (MODE == 0) {
                            o.x += csh[H + klo * H + c0];
                            o.y += csh[H + klo * H + c0 + 1];
                            if (rlo) { o.x += csh[4 * H + c0]; o.y += csh[4 * H + c0 + 1]; }
                        }
                        *(float2*)(dst + (size_t)glo * H + c0) = o;
                    }
                    if (ghi < n) {
                        float2 o = make_float2(acc[mf][nf][2], acc[mf][nf][3]);
                        if (MODE == 0) {
                            o.x += csh[H + khi * H + c0];
                            o.y += csh[H + khi * H + c0 + 1];
                            if (rhi) { o.x += csh[4 * H + c0]; o.y += csh[4 * H + c0 + 1]; }
                        }
                        *(float2*)(dst + (size_t)ghi * H + c0) = o;
                    }
                }
            }
        }
    }
}

// ---------------------------------------------------------------------------
extern "C" void kernel_launch(void* const* d_in, const int* in_sizes, int n_in,
                              void* d_out, int out_size) {
    const float* x          = (const float*)d_in[0];
    const int*   ei         = (const int*)d_in[1];
    const int*   node_kind  = (const int*)d_in[2];
    const float* W_in       = (const float*)d_in[3];
    const float* b_in       = (const float*)d_in[4];
    const float* kind_embed = (const float*)d_in[5];
    const float* ext_seed   = (const float*)d_in[6];
    const float* Wl1        = (const float*)d_in[7];
    const float* bl1        = (const float*)d_in[8];
    const float* Wr1        = (const float*)d_in[9];
    const float* gamma      = (const float*)d_in[10];
    const float* beta       = (const float*)d_in[11];
    const float* Wl2        = (const float*)d_in[12];
    const float* bl2        = (const float*)d_in[13];
    const float* Wr2        = (const float*)d_in[14];

    int n = in_sizes[2];
    int E = in_sizes[1] / 2;

    cudaFuncSetAttribute(tc_gemm<0>, cudaFuncAttributeMaxDynamicSharedMemorySize, SM_BYTES);
    cudaFuncSetAttribute(tc_gemm<1>, cudaFuncAttributeMaxDynamicSharedMemorySize, SM_BYTES);
    cudaFuncSetAttribute(tc_gemm<2>, cudaFuncAttributeMaxDynamicSharedMemorySize, SM_BYTES);

    int ntiles = (n + ROWS_TILE - 1) / ROWS_TILE;
    int ggrid = ntiles < 148 ? ntiles : 148;

    int n4agg = (n * H) / 4;
    int n4cnt = (n + 3) / 4;
    int zgrid = (n4agg + 255) / 256;

    int sthreads = E * 32;
    int sgrid = (sthreads + 255) / 256;

    zero_kernel<<<zgrid, 256>>>(n4agg, n4cnt);
    tc_gemm<0><<<ggrid, TPB, SM_BYTES>>>(x, W_in, nullptr, b_in, kind_embed,
                                         ext_seed, node_kind, nullptr, n);
    scatter_kernel<0, true><<<sgrid, 256>>>(ei, E);
    tc_gemm<1><<<ggrid, TPB, SM_BYTES>>>(nullptr, Wl1, Wr1, bl1, gamma, beta,
                                         nullptr, nullptr, n);
    zero_kernel<<<zgrid, 256>>>(n4agg, 0);
    scatter_kernel<1, false><<<sgrid, 256>>>(ei, E);
    tc_gemm<2><<<ggrid, TPB, SM_BYTES>>>(nullptr, Wl2, Wr2, bl2, nullptr, nullptr,
                                         nullptr, (float*)d_out, n);
}

// round 4
// speedup vs baseline: 1.7705x; 1.6582x over previous
#include <cuda_runtime.h>
#include <cstdint>

#define NMAX 50000
#define H 128
#define KTOT 256
#define TPB 512
#define WSTR 136   // W smem row stride (128+8)

// -------------------- scratch (no allocations allowed) ----------------------
__device__ float g_h0[NMAX * H];
__device__ float g_h1[NMAX * H];
__device__ float g_agg[NMAX * H];
__device__ int   g_cnt[NMAX];

// -------------------- helpers ------------------------------------------------
__device__ __forceinline__ uint32_t tf32r(float x) {
    uint32_t r; asm("cvt.rna.tf32.f32 %0, %1;" : "=r"(r) : "f"(x));
    return r;
}
__device__ __forceinline__ void mma_tf32(float* d, const uint32_t* a, const uint32_t* b) {
    asm volatile("mma.sync.aligned.m16n8k8.row.col.f32.tf32.tf32.f32 "
                 "{%0,%1,%2,%3}, {%4,%5,%6,%7}, {%8,%9}, {%0,%1,%2,%3};"
                 : "+f"(d[0]), "+f"(d[1]), "+f"(d[2]), "+f"(d[3])
                 : "r"(a[0]), "r"(a[1]), "r"(a[2]), "r"(a[3]),
                   "r"(b[0]), "r"(b[1]));
}

// -------------------- zero + scatter -----------------------------------------
__global__ void zero_kernel(int n4agg, int n4cnt) {
    int idx = blockIdx.x * blockDim.x + threadIdx.x;
    if (idx < n4agg) ((float4*)g_agg)[idx] = make_float4(0.f, 0.f, 0.f, 0.f);
    if (idx < n4cnt) ((int4*)g_cnt)[idx] = make_int4(0, 0, 0, 0);
}

template<int SRC, bool DO_CNT>
__global__ void scatter_kernel(const int* __restrict__ ei, int E) {
    int idx = blockIdx.x * blockDim.x + threadIdx.x;
    int total = E * 32;
    if (idx >= total) return;
    int e    = idx >> 5;
    int part = idx & 31;
    int s = __ldg(ei + e);
    int d = __ldg(ei + E + e);
    const float* h = (SRC == 0) ? g_h0 : g_h1;
    float4 v = __ldg((const float4*)(h + (size_t)s * H) + part);
    float4* ap = ((float4*)(g_agg + (size_t)d * H)) + part;
    asm volatile("red.global.add.v4.f32 [%0], {%1,%2,%3,%4};"
                 :: "l"(ap), "f"(v.x), "f"(v.y), "f"(v.z), "f"(v.w)
                 : "memory");
    if (DO_CNT && part == 0) atomicAdd(g_cnt + d, 1);
}

// smem layout (floats)
#define SMF_W     0                       // 2 * 32*136 = 8704
#define SMF_A     8704                    // 2 * 128*32 = 8192
#define SMF_C     16896                   // 768
#define SMF_RS    17664                   // 512
#define SMF_RSS   18176                   // 512
#define SMF_MU    18688                   // 128
#define SMF_RSTD  18816                   // 128
#define SMF_INV   18944                   // 128
#define SMF_KIND  19072                   // 128
#define SMF_TOTAL 19200
#define SM_BYTES  (SMF_TOTAL * 4)

// -------------------- pipelined tf32 mma GEMM + fused epilogue ---------------
// MODE 0: A=x[N,256], W=W_in            -> h0 = ..+b_in+kind_embed[k]+relay*ext
// MODE 1: A=[agg/cnt | h0], W=[Wl1;Wr1] -> relu(LN(..+bl1)) -> h1
// MODE 2: A=[agg/cnt | h1], W=[Wl2;Wr2] -> ..+bl2 -> out
template<int MODE>
__global__ void __launch_bounds__(TPB, 1)
tc_gemm(const float* __restrict__ Aext,
        const float* __restrict__ W0,
        const float* __restrict__ W1,
        const float* __restrict__ bias,
        const float* __restrict__ aux0,   // MODE0 kind_embed / MODE1 gamma
        const float* __restrict__ aux1,   // MODE0 ext_seed   / MODE1 beta
        const int*   __restrict__ node_kind,
        float* __restrict__ outExt,
        int n)
{
    extern __shared__ float sm[];
    float* Wbuf[2] = { sm + SMF_W, sm + SMF_W + 32 * WSTR };
    float* Abuf[2] = { sm + SMF_A, sm + SMF_A + 128 * 32 };
    float* csh   = sm + SMF_C;
    float* rs    = sm + SMF_RS;
    float* rss   = sm + SMF_RSS;
    float* mus   = sm + SMF_MU;
    float* rstds = sm + SMF_RSTD;
    float* invsh = sm + SMF_INV;
    int*   kindsh = (int*)(sm + SMF_KIND);

    const int tid = threadIdx.x;
    const int wid = tid >> 5;
    const int lid = tid & 31;
    const int lq = lid >> 2;
    const int lr = lid & 3;
    const int wr = wid & 3;        // 4 row-blocks of 32
    const int cw = wid >> 2;       // 4 col-blocks of 32
    const int row0 = blockIdx.x << 7;

    // staging thread roles
    const int arow = tid >> 2;     // 0..127
    const int ag   = tid & 3;      // k-group of 8
    const int agr  = row0 + arow;
    const int wk   = tid >> 4;     // 0..31 (k row within chunk)
    const int wq   = (tid & 15) * 2;  // float4 idx

    const float* Asrc = (MODE == 1) ? (const float*)g_h0 : (const float*)g_h1;

    float4 va, vb, wa, wb;

    // ---- LDG lambdas (manual) ----
    auto ldgA = [&](int ch) {
        va = make_float4(0.f,0.f,0.f,0.f); vb = va;
        if (agr < n) {
            if (MODE == 0) {
                const float4* s = (const float4*)(Aext + (size_t)agr * KTOT + ch * 32 + ag * 8);
                va = __ldg(s); vb = __ldg(s + 1);
            } else if (ch < 4) {
                const float4* s = (const float4*)(g_agg + (size_t)agr * H + ch * 32 + ag * 8);
                va = __ldg(s); vb = __ldg(s + 1);
            } else {
                const float4* s = (const float4*)(Asrc + (size_t)agr * H + (ch - 4) * 32 + ag * 8);
                va = __ldg(s); vb = __ldg(s + 1);
            }
        }
    };
    auto stsA = [&](int ch, int p) {
        float scv = 1.f;
        if (MODE != 0 && ch < 4) scv = invsh[arow];
        uint4 s0, s1;
        s0.x = tf32r(va.x * scv); s0.y = tf32r(vb.x * scv);
        s0.z = tf32r(va.y * scv); s0.w = tf32r(vb.y * scv);
        s1.x = tf32r(va.z * scv); s1.y = tf32r(vb.z * scv);
        s1.z = tf32r(va.w * scv); s1.w = tf32r(vb.w * scv);
        int u0 = (ag * 2) ^ ((arow & 3) << 1);
        uint4* d = (uint4*)&Abuf[p][arow * 32 + u0 * 4];
        d[0] = s0; d[1] = s1;
    };
    auto ldgW = [&](int ch) {
        int gk = ch * 32 + wk;
        const float* wrow;
        if (MODE == 0)      wrow = W0 + (size_t)gk * H;
        else if (gk < H)    wrow = W0 + (size_t)gk * H;
        else                wrow = W1 + (size_t)(gk - H) * H;
        wa = __ldg((const float4*)wrow + wq);
        wb = __ldg((const float4*)wrow + wq + 1);
    };
    auto stsW = [&](int p) {
        uint4 ta, tb;
        ta.x = tf32r(wa.x); ta.y = tf32r(wa.y); ta.z = tf32r(wa.z); ta.w = tf32r(wa.w);
        tb.x = tf32r(wb.x); tb.y = tf32r(wb.y); tb.z = tf32r(wb.z); tb.w = tf32r(wb.w);
        uint4* d = (uint4*)&Wbuf[p][wk * WSTR + wq * 4];
        d[0] = ta; d[1] = tb;
    };

    // ---- prologue: consts + chunk0 ----
    ldgA(0); ldgW(0);
    if (tid < H) csh[tid] = __ldg(bias + tid);
    if (MODE == 0) {
        if (tid >= H && tid < H + 3 * H) csh[tid] = __ldg(aux0 + (tid - H));
        if (tid < H) csh[4 * H + tid] = __ldg(aux1 + tid);
        if (tid < 128) kindsh[tid] = (row0 + tid < n) ? __ldg(node_kind + row0 + tid) : 0;
    } else if (MODE == 1) {
        if (tid < H) { csh[H + tid] = __ldg(aux0 + tid); csh[2 * H + tid] = __ldg(aux1 + tid); }
    }
    if (MODE != 0 && tid < 128) {
        int r = row0 + tid;
        int c = (r < n) ? g_cnt[r] : 1;
        if (c < 1) c = 1;
        invsh[tid] = 1.0f / (float)c;
    }
    __syncthreads();
    stsA(0, 0); stsW(0);
    ldgA(1); ldgW(1);
    __syncthreads();

    float acc[2][4][4];
    #pragma unroll
    for (int mf = 0; mf < 2; mf++)
        #pragma unroll
        for (int nf = 0; nf < 4; nf++)
            #pragma unroll
            for (int q = 0; q < 4; q++) acc[mf][nf][q] = 0.f;

    int p = 0;
    #pragma unroll
    for (int ch = 0; ch < 8; ch++) {
        // ---- MMA on buffer p ----
        const float* Ab = Abuf[p];
        const float* Wb = Wbuf[p];
        #pragma unroll
        for (int ks = 0; ks < 4; ks++) {
            uint32_t a[2][4];
            #pragma unroll
            for (int mf = 0; mf < 2; mf++) {
                int rlo = wr * 32 + mf * 16 + lq;
                int u = (ks * 2 + (lr >> 1)) ^ ((lq & 3) << 1);
                float2 lo = *(const float2*)&Ab[rlo * 32 + u * 4 + (lr & 1) * 2];
                float2 hi = *(const float2*)&Ab[(rlo + 8) * 32 + u * 4 + (lr & 1) * 2];
                a[mf][0] = __float_as_uint(lo.x);
                a[mf][1] = __float_as_uint(hi.x);
                a[mf][2] = __float_as_uint(lo.y);
                a[mf][3] = __float_as_uint(hi.y);
            }
            uint32_t b[4][2];
            #pragma unroll
            for (int nf = 0; nf < 4; nf++) {
                const uint32_t* bp =
                    (const uint32_t*)&Wb[(ks * 8 + lr) * WSTR + cw * 32 + nf * 8 + lq];
                b[nf][0] = bp[0];
                b[nf][1] = bp[4 * WSTR];
            }
            #pragma unroll
            for (int mf = 0; mf < 2; mf++)
                #pragma unroll
                for (int nf = 0; nf < 4; nf++)
                    mma_tf32(acc[mf][nf], a[mf], b[nf]);
        }
        if (ch < 7) {
            stsA(ch + 1, p ^ 1); stsW(p ^ 1);
            if (ch < 6) { ldgA(ch + 2); ldgW(ch + 2); }
        }
        __syncthreads();
        p ^= 1;
    }

    // ---------------- epilogue ----------------
    #pragma unroll
    for (int mf = 0; mf < 2; mf++)
        #pragma unroll
        for (int nf = 0; nf < 4; nf++) {
            int c0 = cw * 32 + nf * 8 + 2 * lr;
            float b0v = csh[c0], b1v = csh[c0 + 1];
            acc[mf][nf][0] += b0v; acc[mf][nf][1] += b1v;
            acc[mf][nf][2] += b0v; acc[mf][nf][3] += b1v;
        }

    if (MODE == 1) {
        #pragma unroll
        for (int mf = 0; mf < 2; mf++) {
            float slo = 0.f, sslo = 0.f, shi = 0.f, sshi = 0.f;
            #pragma unroll
            for (int nf = 0; nf < 4; nf++) {
                float v0 = acc[mf][nf][0], v1 = acc[mf][nf][1];
                float v2 = acc[mf][nf][2], v3 = acc[mf][nf][3];
                slo += v0 + v1;  sslo += v0 * v0 + v1 * v1;
                shi += v2 + v3;  sshi += v2 * v2 + v3 * v3;
            }
            #pragma unroll
            for (int m = 1; m <= 2; m <<= 1) {
                slo  += __shfl_xor_sync(0xffffffffu, slo,  m);
                sslo += __shfl_xor_sync(0xffffffffu, sslo, m);
                shi  += __shfl_xor_sync(0xffffffffu, shi,  m);
                sshi += __shfl_xor_sync(0xffffffffu, sshi, m);
            }
            if (lr == 0) {
                int rlo = wr * 32 + mf * 16 + lq;
                rs [rlo * 4 + cw] = slo;       rss[rlo * 4 + cw] = sslo;
                rs [(rlo + 8) * 4 + cw] = shi; rss[(rlo + 8) * 4 + cw] = sshi;
            }
        }
        __syncthreads();
        if (tid < 128) {
            float s  = rs [tid * 4] + rs [tid * 4 + 1] + rs [tid * 4 + 2] + rs [tid * 4 + 3];
            float ss = rss[tid * 4] + rss[tid * 4 + 1] + rss[tid * 4 + 2] + rss[tid * 4 + 3];
            float mu  = s * (1.0f / H);
            float var = ss * (1.0f / H) - mu * mu;
            mus[tid] = mu;
            rstds[tid] = rsqrtf(var + 1e-5f);
        }
        __syncthreads();
        #pragma unroll
        for (int mf = 0; mf < 2; mf++) {
            int lrow = wr * 32 + mf * 16 + lq;
            float mu_lo = mus[lrow],     rd_lo = rstds[lrow];
            float mu_hi = mus[lrow + 8], rd_hi = rstds[lrow + 8];
            int glo = row0 + lrow, ghi = glo + 8;
            #pragma unroll
            for (int nf = 0; nf < 4; nf++) {
                int c0 = cw * 32 + nf * 8 + 2 * lr;
                float g0 = csh[H + c0], g1 = csh[H + c0 + 1];
                float be0 = csh[2 * H + c0], be1 = csh[2 * H + c0 + 1];
                if (glo < n) {
                    float2 o;
                    o.x = fmaxf((acc[mf][nf][0] - mu_lo) * rd_lo * g0 + be0, 0.f);
                    o.y = fmaxf((acc[mf][nf][1] - mu_lo) * rd_lo * g1 + be1, 0.f);
                    *(float2*)(g_h1 + (size_t)glo * H + c0) = o;
                }
                if (ghi < n) {
                    float2 o;
                    o.x = fmaxf((acc[mf][nf][2] - mu_hi) * rd_hi * g0 + be0, 0.f);
                    o.y = fmaxf((acc[mf][nf][3] - mu_hi) * rd_hi * g1 + be1, 0.f);
                    *(float2*)(g_h1 + (size_t)ghi * H + c0) = o;
                }
            }
        }
    } else {
        #pragma unroll
        for (int mf = 0; mf < 2; mf++) {
            int lrow = wr * 32 + mf * 16 + lq;
            int glo = row0 + lrow, ghi = glo + 8;
            int klo = 0, khi = 0;
            bool rlo = false, rhi = false;
            if (MODE == 0) {
                klo = kindsh[lrow]; khi = kindsh[lrow + 8];
                rlo = (klo != 0);   rhi = (khi != 0);
            }
            float* dst = (MODE == 0) ? g_h0 : outExt;
            #pragma unroll
            for (int nf = 0; nf < 4; nf++) {
                int c0 = cw * 32 + nf * 8 + 2 * lr;
                if (glo < n) {
                    float2 o = make_float2(acc[mf][nf][0], acc[mf][nf][1]);
                    if (MODE == 0) {
                        o.x += csh[H + klo * H + c0];
                        o.y += csh[H + klo * H + c0 + 1];
                        if (rlo) { o.x += csh[4 * H + c0]; o.y += csh[4 * H + c0 + 1]; }
                    }
                    *(float2*)(dst + (size_t)glo * H + c0) = o;
                }
                if (ghi < n) {
                    float2 o = make_float2(acc[mf][nf][2], acc[mf][nf][3]);
                    if (MODE == 0) {
                        o.x += csh[H + khi * H + c0];
                        o.y += csh[H + khi * H + c0 + 1];
                        if (rhi) { o.x += csh[4 * H + c0]; o.y += csh[4 * H + c0 + 1]; }
                    }
                    *(float2*)(dst + (size_t)ghi * H + c0) = o;
                }
            }
        }
    }
}

// ---------------------------------------------------------------------------
extern "C" void kernel_launch(void* const* d_in, const int* in_sizes, int n_in,
                              void* d_out, int out_size) {
    const float* x          = (const float*)d_in[0];
    const int*   ei         = (const int*)d_in[1];
    const int*   node_kind  = (const int*)d_in[2];
    const float* W_in       = (const float*)d_in[3];
    const float* b_in       = (const float*)d_in[4];
    const float* kind_embed = (const float*)d_in[5];
    const float* ext_seed   = (const float*)d_in[6];
    const float* Wl1        = (const float*)d_in[7];
    const float* bl1        = (const float*)d_in[8];
    const float* Wr1        = (const float*)d_in[9];
    const float* gamma      = (const float*)d_in[10];
    const float* beta       = (const float*)d_in[11];
    const float* Wl2        = (const float*)d_in[12];
    const float* bl2        = (const float*)d_in[13];
    const float* Wr2        = (const float*)d_in[14];

    int n = in_sizes[2];
    int E = in_sizes[1] / 2;

    cudaFuncSetAttribute(tc_gemm<0>, cudaFuncAttributeMaxDynamicSharedMemorySize, SM_BYTES);
    cudaFuncSetAttribute(tc_gemm<1>, cudaFuncAttributeMaxDynamicSharedMemorySize, SM_BYTES);
    cudaFuncSetAttribute(tc_gemm<2>, cudaFuncAttributeMaxDynamicSharedMemorySize, SM_BYTES);

    int ntiles = (n + 127) / 128;

    int n4agg = (n * H) / 4;
    int n4cnt = (n + 3) / 4;
    int zgrid = (n4agg + 255) / 256;

    int sthreads = E * 32;
    int sgrid = (sthreads + 255) / 256;

    zero_kernel<<<zgrid, 256>>>(n4agg, n4cnt);
    tc_gemm<0><<<ntiles, TPB, SM_BYTES>>>(x, W_in, nullptr, b_in, kind_embed,
                                          ext_seed, node_kind, nullptr, n);
    scatter_kernel<0, true><<<sgrid, 256>>>(ei, E);
    tc_gemm<1><<<ntiles, TPB, SM_BYTES>>>(nullptr, Wl1, Wr1, bl1, gamma, beta,
                                          nullptr, nullptr, n);
    zero_kernel<<<zgrid, 256>>>(n4agg, 0);
    scatter_kernel<1, false><<<sgrid, 256>>>(ei, E);
    tc_gemm<2><<<ntiles, TPB, SM_BYTES>>>(nullptr, Wl2, Wr2, bl2, nullptr, nullptr,
                                          nullptr, (float*)d_out, n);
}

// round 5
// speedup vs baseline: 2.4686x; 1.3943x over previous
#include <cuda_runtime.h>
#include <cstdint>

#define NMAX 50000
#define EMAX 650000
#define H 128
#define KTOT 256
#define TPB 512
#define WSTR 136   // W smem row stride (128+8)

// -------------------- scratch (no allocations allowed) ----------------------
__device__ float g_h0[NMAX * H];
__device__ float g_h1[NMAX * H];
__device__ float g_agg[NMAX * H];
__device__ int   g_cnt[NMAX];
__device__ int   g_off[NMAX];
__device__ int   g_cur[NMAX];
__device__ int   g_adj[EMAX];
__device__ int   g_blk[256];

// -------------------- helpers ------------------------------------------------
__device__ __forceinline__ uint32_t tf32r(float x) {
    uint32_t r; asm("cvt.rna.tf32.f32 %0, %1;" : "=r"(r) : "f"(x));
    return r;
}
__device__ __forceinline__ void mma_tf32(float* d, const uint32_t* a, const uint32_t* b) {
    asm volatile("mma.sync.aligned.m16n8k8.row.col.f32.tf32.tf32.f32 "
                 "{%0,%1,%2,%3}, {%4,%5,%6,%7}, {%8,%9}, {%0,%1,%2,%3};"
                 : "+f"(d[0]), "+f"(d[1]), "+f"(d[2]), "+f"(d[3])
                 : "r"(a[0]), "r"(a[1]), "r"(a[2]), "r"(a[3]),
                   "r"(b[0]), "r"(b[1]));
}

// -------------------- CSR build ----------------------------------------------
__global__ void zero_cnt(int n) {
    int i = blockIdx.x * blockDim.x + threadIdx.x;
    if (i < n) g_cnt[i] = 0;
}
__global__ void hist_kernel(const int* __restrict__ ei, int E) {
    int e = blockIdx.x * blockDim.x + threadIdx.x;
    if (e < E) atomicAdd(&g_cnt[__ldg(ei + E + e)], 1);
}
// per-block exclusive scan of 256 counts; block total -> g_blk
__global__ void scan1(int n) {
    __shared__ int smv[256];
    int t = threadIdx.x;
    int i = blockIdx.x * 256 + t;
    int v = (i < n) ? g_cnt[i] : 0;
    smv[t] = v;
    __syncthreads();
    #pragma unroll
    for (int off = 1; off < 256; off <<= 1) {
        int x = (t >= off) ? smv[t - off] : 0;
        __syncthreads();
        smv[t] += x;
        __syncthreads();
    }
    if (i < n) g_off[i] = smv[t] - v;
    if (t == 255) g_blk[blockIdx.x] = smv[255];
}
__global__ void scan2(int nb) {
    __shared__ int smv[256];
    int t = threadIdx.x;
    int v = (t < nb) ? g_blk[t] : 0;
    smv[t] = v;
    __syncthreads();
    #pragma unroll
    for (int off = 1; off < 256; off <<= 1) {
        int x = (t >= off) ? smv[t - off] : 0;
        __syncthreads();
        smv[t] += x;
        __syncthreads();
    }
    if (t < nb) g_blk[t] = smv[t] - v;
}
__global__ void scan3(int n) {
    int i = blockIdx.x * blockDim.x + threadIdx.x;
    if (i < n) {
        int o = g_off[i] + g_blk[i >> 8];
        g_off[i] = o;
        g_cur[i] = o;
    }
}
__global__ void fill_kernel(const int* __restrict__ ei, int E) {
    int e = blockIdx.x * blockDim.x + threadIdx.x;
    if (e < E) {
        int s = __ldg(ei + e);
        int d = __ldg(ei + E + e);
        int p = atomicAdd(&g_cur[d], 1);
        g_adj[p] = s;
    }
}

// -------------------- CSR aggregate: mean of h[src] per dst ------------------
// one warp per node; SRC 0 -> g_h0, 1 -> g_h1
template<int SRC>
__global__ void aggregate_kernel(int n) {
    int gw = (blockIdx.x * blockDim.x + threadIdx.x) >> 5;
    if (gw >= n) return;
    int lane = threadIdx.x & 31;
    const float* h = (SRC == 0) ? g_h0 : g_h1;
    int start = g_off[gw];
    int c = g_cnt[gw];
    float4 acc0 = make_float4(0.f, 0.f, 0.f, 0.f);
    float4 acc1 = make_float4(0.f, 0.f, 0.f, 0.f);
    int j = 0;
    for (; j + 2 <= c; j += 2) {
        int s0 = __ldg(g_adj + start + j);
        int s1 = __ldg(g_adj + start + j + 1);
        float4 v0 = __ldg((const float4*)(h + (size_t)s0 * H) + lane);
        float4 v1 = __ldg((const float4*)(h + (size_t)s1 * H) + lane);
        acc0.x += v0.x; acc0.y += v0.y; acc0.z += v0.z; acc0.w += v0.w;
        acc1.x += v1.x; acc1.y += v1.y; acc1.z += v1.z; acc1.w += v1.w;
    }
    if (j < c) {
        int s0 = __ldg(g_adj + start + j);
        float4 v0 = __ldg((const float4*)(h + (size_t)s0 * H) + lane);
        acc0.x += v0.x; acc0.y += v0.y; acc0.z += v0.z; acc0.w += v0.w;
    }
    float sc = (c > 0) ? (1.0f / (float)c) : 0.0f;
    float4 o;
    o.x = (acc0.x + acc1.x) * sc;
    o.y = (acc0.y + acc1.y) * sc;
    o.z = (acc0.z + acc1.z) * sc;
    o.w = (acc0.w + acc1.w) * sc;
    ((float4*)(g_agg + (size_t)gw * H))[lane] = o;
}

// smem layout (floats)
#define SMF_W     0                       // 2 * 32*136 = 8704
#define SMF_A     8704                    // 2 * 128*32 = 8192
#define SMF_C     16896                   // 768
#define SMF_RS    17664                   // 512
#define SMF_RSS   18176                   // 512
#define SMF_MU    18688                   // 128
#define SMF_RSTD  18816                   // 128
#define SMF_KIND  18944                   // 128
#define SMF_TOTAL 19072
#define SM_BYTES  (SMF_TOTAL * 4)

// -------------------- pipelined tf32 mma GEMM + fused epilogue ---------------
// MODE 0: A=x[N,256], W=W_in            -> h0 = ..+b_in+kind_embed[k]+relay*ext
// MODE 1: A=[agg | h0], W=[Wl1;Wr1]     -> relu(LN(..+bl1)) -> h1
// MODE 2: A=[agg | h1], W=[Wl2;Wr2]     -> ..+bl2 -> out
template<int MODE>
__global__ void __launch_bounds__(TPB, 1)
tc_gemm(const float* __restrict__ Aext,
        const float* __restrict__ W0,
        const float* __restrict__ W1,
        const float* __restrict__ bias,
        const float* __restrict__ aux0,   // MODE0 kind_embed / MODE1 gamma
        const float* __restrict__ aux1,   // MODE0 ext_seed   / MODE1 beta
        const int*   __restrict__ node_kind,
        float* __restrict__ outExt,
        int n)
{
    extern __shared__ float sm[];
    float* Wbuf[2] = { sm + SMF_W, sm + SMF_W + 32 * WSTR };
    float* Abuf[2] = { sm + SMF_A, sm + SMF_A + 128 * 32 };
    float* csh   = sm + SMF_C;
    float* rs    = sm + SMF_RS;
    float* rss   = sm + SMF_RSS;
    float* mus   = sm + SMF_MU;
    float* rstds = sm + SMF_RSTD;
    int*   kindsh = (int*)(sm + SMF_KIND);

    const int tid = threadIdx.x;
    const int wid = tid >> 5;
    const int lid = tid & 31;
    const int lq = lid >> 2;
    const int lr = lid & 3;
    const int wr = wid & 3;        // 4 row-blocks of 32
    const int cw = wid >> 2;       // 4 col-blocks of 32
    const int row0 = blockIdx.x << 7;

    // staging thread roles
    const int arow = tid >> 2;     // 0..127
    const int ag   = tid & 3;      // k-group of 8
    const int agr  = row0 + arow;
    const int wk   = tid >> 4;     // 0..31 (k row within chunk)
    const int wq   = (tid & 15) * 2;  // float4 idx

    const float* Asrc = (MODE == 1) ? (const float*)g_h0 : (const float*)g_h1;

    float4 va, vb, wa, wb;

    auto ldgA = [&](int ch) {
        va = make_float4(0.f,0.f,0.f,0.f); vb = va;
        if (agr < n) {
            if (MODE == 0) {
                const float4* s = (const float4*)(Aext + (size_t)agr * KTOT + ch * 32 + ag * 8);
                va = __ldg(s); vb = __ldg(s + 1);
            } else if (ch < 4) {
                const float4* s = (const float4*)(g_agg + (size_t)agr * H + ch * 32 + ag * 8);
                va = __ldg(s); vb = __ldg(s + 1);
            } else {
                const float4* s = (const float4*)(Asrc + (size_t)agr * H + (ch - 4) * 32 + ag * 8);
                va = __ldg(s); vb = __ldg(s + 1);
            }
        }
    };
    auto stsA = [&](int ch, int p) {
        uint4 s0, s1;
        s0.x = tf32r(va.x); s0.y = tf32r(vb.x);
        s0.z = tf32r(va.y); s0.w = tf32r(vb.y);
        s1.x = tf32r(va.z); s1.y = tf32r(vb.z);
        s1.z = tf32r(va.w); s1.w = tf32r(vb.w);
        int u0 = (ag * 2) ^ ((arow & 3) << 1);
        uint4* d = (uint4*)&Abuf[p][arow * 32 + u0 * 4];
        d[0] = s0; d[1] = s1;
    };
    auto ldgW = [&](int ch) {
        int gk = ch * 32 + wk;
        const float* wrow;
        if (MODE == 0)      wrow = W0 + (size_t)gk * H;
        else if (gk < H)    wrow = W0 + (size_t)gk * H;
        else                wrow = W1 + (size_t)(gk - H) * H;
        wa = __ldg((const float4*)wrow + wq);
        wb = __ldg((const float4*)wrow + wq + 1);
    };
    auto stsW = [&](int p) {
        uint4 ta, tb;
        ta.x = tf32r(wa.x); ta.y = tf32r(wa.y); ta.z = tf32r(wa.z); ta.w = tf32r(wa.w);
        tb.x = tf32r(wb.x); tb.y = tf32r(wb.y); tb.z = tf32r(wb.z); tb.w = tf32r(wb.w);
        uint4* d = (uint4*)&Wbuf[p][wk * WSTR + wq * 4];
        d[0] = ta; d[1] = tb;
    };

    // ---- prologue ----
    ldgA(0); ldgW(0);
    if (tid < H) csh[tid] = __ldg(bias + tid);
    if (MODE == 0) {
        if (tid >= H && tid < H + 3 * H) csh[tid] = __ldg(aux0 + (tid - H));
        if (tid < H) csh[4 * H + tid] = __ldg(aux1 + tid);
        if (tid < 128) kindsh[tid] = (row0 + tid < n) ? __ldg(node_kind + row0 + tid) : 0;
    } else if (MODE == 1) {
        if (tid < H) { csh[H + tid] = __ldg(aux0 + tid); csh[2 * H + tid] = __ldg(aux1 + tid); }
    }
    __syncthreads();
    stsA(0, 0); stsW(0);
    ldgA(1); ldgW(1);
    __syncthreads();

    float acc[2][4][4];
    #pragma unroll
    for (int mf = 0; mf < 2; mf++)
        #pragma unroll
        for (int nf = 0; nf < 4; nf++)
            #pragma unroll
            for (int q = 0; q < 4; q++) acc[mf][nf][q] = 0.f;

    int p = 0;
    #pragma unroll
    for (int ch = 0; ch < 8; ch++) {
        const float* Ab = Abuf[p];
        const float* Wb = Wbuf[p];
        #pragma unroll
        for (int ks = 0; ks < 4; ks++) {
            uint32_t a[2][4];
            #pragma unroll
            for (int mf = 0; mf < 2; mf++) {
                int rlo = wr * 32 + mf * 16 + lq;
                int u = (ks * 2 + (lr >> 1)) ^ ((lq & 3) << 1);
                float2 lo = *(const float2*)&Ab[rlo * 32 + u * 4 + (lr & 1) * 2];
                float2 hi = *(const float2*)&Ab[(rlo + 8) * 32 + u * 4 + (lr & 1) * 2];
                a[mf][0] = __float_as_uint(lo.x);
                a[mf][1] = __float_as_uint(hi.x);
                a[mf][2] = __float_as_uint(lo.y);
                a[mf][3] = __float_as_uint(hi.y);
            }
            uint32_t b[4][2];
            #pragma unroll
            for (int nf = 0; nf < 4; nf++) {
                const uint32_t* bp =
                    (const uint32_t*)&Wb[(ks * 8 + lr) * WSTR + cw * 32 + nf * 8 + lq];
                b[nf][0] = bp[0];
                b[nf][1] = bp[4 * WSTR];
            }
            #pragma unroll
            for (int mf = 0; mf < 2; mf++)
                #pragma unroll
                for (int nf = 0; nf < 4; nf++)
                    mma_tf32(acc[mf][nf], a[mf], b[nf]);
        }
        if (ch < 7) {
            stsA(ch + 1, p ^ 1); stsW(p ^ 1);
            if (ch < 6) { ldgA(ch + 2); ldgW(ch + 2); }
        }
        __syncthreads();
        p ^= 1;
    }

    // ---------------- epilogue ----------------
    #pragma unroll
    for (int mf = 0; mf < 2; mf++)
        #pragma unroll
        for (int nf = 0; nf < 4; nf++) {
            int c0 = cw * 32 + nf * 8 + 2 * lr;
            float b0v = csh[c0], b1v = csh[c0 + 1];
            acc[mf][nf][0] += b0v; acc[mf][nf][1] += b1v;
            acc[mf][nf][2] += b0v; acc[mf][nf][3] += b1v;
        }

    if (MODE == 1) {
        #pragma unroll
        for (int mf = 0; mf < 2; mf++) {
            float slo = 0.f, sslo = 0.f, shi = 0.f, sshi = 0.f;
            #pragma unroll
            for (int nf = 0; nf < 4; nf++) {
                float v0 = acc[mf][nf][0], v1 = acc[mf][nf][1];
                float v2 = acc[mf][nf][2], v3 = acc[mf][nf][3];
                slo += v0 + v1;  sslo += v0 * v0 + v1 * v1;
                shi += v2 + v3;  sshi += v2 * v2 + v3 * v3;
            }
            #pragma unroll
            for (int m = 1; m <= 2; m <<= 1) {
                slo  += __shfl_xor_sync(0xffffffffu, slo,  m);
                sslo += __shfl_xor_sync(0xffffffffu, sslo, m);
                shi  += __shfl_xor_sync(0xffffffffu, shi,  m);
                sshi += __shfl_xor_sync(0xffffffffu, sshi, m);
            }
            if (lr == 0) {
                int rlo = wr * 32 + mf * 16 + lq;
                rs [rlo * 4 + cw] = slo;       rss[rlo * 4 + cw] = sslo;
                rs [(rlo + 8) * 4 + cw] = shi; rss[(rlo + 8) * 4 + cw] = sshi;
            }
        }
        __syncthreads();
        if (tid < 128) {
            float s  = rs [tid * 4] + rs [tid * 4 + 1] + rs [tid * 4 + 2] + rs [tid * 4 + 3];
            float ss = rss[tid * 4] + rss[tid * 4 + 1] + rss[tid * 4 + 2] + rss[tid * 4 + 3];
            float mu  = s * (1.0f / H);
            float var = ss * (1.0f / H) - mu * mu;
            mus[tid] = mu;
            rstds[tid] = rsqrtf(var + 1e-5f);
        }
        __syncthreads();
        #pragma unroll
        for (int mf = 0; mf < 2; mf++) {
            int lrow = wr * 32 + mf * 16 + lq;
            float mu_lo = mus[lrow],     rd_lo = rstds[lrow];
            float mu_hi = mus[lrow + 8], rd_hi = rstds[lrow + 8];
            int glo = row0 + lrow, ghi = glo + 8;
            #pragma unroll
            for (int nf = 0; nf < 4; nf++) {
                int c0 = cw * 32 + nf * 8 + 2 * lr;
                float g0 = csh[H + c0], g1 = csh[H + c0 + 1];
                float be0 = csh[2 * H + c0], be1 = csh[2 * H + c0 + 1];
                if (glo < n) {
                    float2 o;
                    o.x = fmaxf((acc[mf][nf][0] - mu_lo) * rd_lo * g0 + be0, 0.f);
                    o.y = fmaxf((acc[mf][nf][1] - mu_lo) * rd_lo * g1 + be1, 0.f);
                    *(float2*)(g_h1 + (size_t)glo * H + c0) = o;
                }
                if (ghi < n) {
                    float2 o;
                    o.x = fmaxf((acc[mf][nf][2] - mu_hi) * rd_hi * g0 + be0, 0.f);
                    o.y = fmaxf((acc[mf][nf][3] - mu_hi) * rd_hi * g1 + be1, 0.f);
                    *(float2*)(g_h1 + (size_t)ghi * H + c0) = o;
                }
            }
        }
    } else {
        #pragma unroll
        for (int mf = 0; mf < 2; mf++) {
            int lrow = wr * 32 + mf * 16 + lq;
            int glo = row0 + lrow, ghi = glo + 8;
            int klo = 0, khi = 0;
            bool rlo = false, rhi = false;
            if (MODE == 0) {
                klo = kindsh[lrow]; khi = kindsh[lrow + 8];
                rlo = (klo != 0);   rhi = (khi != 0);
            }
            float* dst = (MODE == 0) ? g_h0 : outExt;
            #pragma unroll
            for (int nf = 0; nf < 4; nf++) {
                int c0 = cw * 32 + nf * 8 + 2 * lr;
                if (glo < n) {
                    float2 o = make_float2(acc[mf][nf][0], acc[mf][nf][1]);
                    if (MODE == 0) {
                        o.x += csh[H + klo * H + c0];
                        o.y += csh[H + klo * H + c0 + 1];
                        if (rlo) { o.x += csh[4 * H + c0]; o.y += csh[4 * H + c0 + 1]; }
                    }
                    *(float2*)(dst + (size_t)glo * H + c0) = o;
                }
                if (ghi < n) {
                    float2 o = make_float2(acc[mf][nf][2], acc[mf][nf][3]);
                    if (MODE == 0) {
                        o.x += csh[H + khi * H + c0];
                        o.y += csh[H + khi * H + c0 + 1];
                        if (rhi) { o.x += csh[4 * H + c0]; o.y += csh[4 * H + c0 + 1]; }
                    }
                    *(float2*)(dst + (size_t)ghi * H + c0) = o;
                }
            }
        }
    }
}

// ---------------------------------------------------------------------------
extern "C" void kernel_launch(void* const* d_in, const int* in_sizes, int n_in,
                              void* d_out, int out_size) {
    const float* x          = (const float*)d_in[0];
    const int*   ei         = (const int*)d_in[1];
    const int*   node_kind  = (const int*)d_in[2];
    const float* W_in       = (const float*)d_in[3];
    const float* b_in       = (const float*)d_in[4];
    const float* kind_embed = (const float*)d_in[5];
    const float* ext_seed   = (const float*)d_in[6];
    const float* Wl1        = (const float*)d_in[7];
    const float* bl1        = (const float*)d_in[8];
    const float* Wr1        = (const float*)d_in[9];
    const float* gamma      = (const float*)d_in[10];
    const float* beta       = (const float*)d_in[11];
    const float* Wl2        = (const float*)d_in[12];
    const float* bl2        = (const float*)d_in[13];
    const float* Wr2        = (const float*)d_in[14];

    int n = in_sizes[2];
    int E = in_sizes[1] / 2;

    cudaFuncSetAttribute(tc_gemm<0>, cudaFuncAttributeMaxDynamicSharedMemorySize, SM_BYTES);
    cudaFuncSetAttribute(tc_gemm<1>, cudaFuncAttributeMaxDynamicSharedMemorySize, SM_BYTES);
    cudaFuncSetAttribute(tc_gemm<2>, cudaFuncAttributeMaxDynamicSharedMemorySize, SM_BYTES);

    int ntiles = (n + 127) / 128;
    int nb256  = (n + 255) / 256;
    int eb256  = (E + 255) / 256;
    int aggblk = (n * 32 + 255) / 256;

    // ---- CSR build (shared by both conv layers) ----
    zero_cnt<<<nb256, 256>>>(n);
    hist_kernel<<<eb256, 256>>>(ei, E);
    scan1<<<nb256, 256>>>(n);
    scan2<<<1, 256>>>(nb256);
    scan3<<<nb256, 256>>>(n);
    fill_kernel<<<eb256, 256>>>(ei, E);

    // ---- pipeline ----
    tc_gemm<0><<<ntiles, TPB, SM_BYTES>>>(x, W_in, nullptr, b_in, kind_embed,
                                          ext_seed, node_kind, nullptr, n);
    aggregate_kernel<0><<<aggblk, 256>>>(n);
    tc_gemm<1><<<ntiles, TPB, SM_BYTES>>>(nullptr, Wl1, Wr1, bl1, gamma, beta,
                                          nullptr, nullptr, n);
    aggregate_kernel<1><<<aggblk, 256>>>(n);
    tc_gemm<2><<<ntiles, TPB, SM_BYTES>>>(nullptr, Wl2, Wr2, bl2, nullptr, nullptr,
                                          nullptr, (float*)d_out, n);
}

// round 6
// speedup vs baseline: 2.7266x; 1.1045x over previous
#include <cuda_runtime.h>
#include <cstdint>

#define NMAX 50000
#define EMAX 650000
#define H 128
#define KTOT 256
#define TPB 512

// -------------------- scratch (no allocations allowed) ----------------------
__device__ float g_h0[NMAX * H];
__device__ float g_h1[NMAX * H];
__device__ float g_agg[NMAX * H];
__device__ int   g_cnt[NMAX];
__device__ int   g_off[NMAX];
__device__ int   g_cur[NMAX];
__device__ int   g_adj[EMAX];
__device__ int   g_blk[256];

// -------------------- helpers ------------------------------------------------
__device__ __forceinline__ uint32_t tf32r(float x) {
    uint32_t r; asm("cvt.rna.tf32.f32 %0, %1;" : "=r"(r) : "f"(x));
    return r;
}
__device__ __forceinline__ void mma_tf32(float* d, const uint32_t* a, const uint32_t* b) {
    asm volatile("mma.sync.aligned.m16n8k8.row.col.f32.tf32.tf32.f32 "
                 "{%0,%1,%2,%3}, {%4,%5,%6,%7}, {%8,%9}, {%0,%1,%2,%3};"
                 : "+f"(d[0]), "+f"(d[1]), "+f"(d[2]), "+f"(d[3])
                 : "r"(a[0]), "r"(a[1]), "r"(a[2]), "r"(a[3]),
                   "r"(b[0]), "r"(b[1]));
}

// -------------------- CSR build ----------------------------------------------
__global__ void zero_cnt(int n) {
    int i = blockIdx.x * blockDim.x + threadIdx.x;
    if (i < n) g_cnt[i] = 0;
}
__global__ void hist_kernel(const int* __restrict__ ei, int E) {
    int e = blockIdx.x * blockDim.x + threadIdx.x;
    if (e < E) atomicAdd(&g_cnt[__ldg(ei + E + e)], 1);
}
__global__ void scan1(int n) {
    __shared__ int smv[256];
    int t = threadIdx.x;
    int i = blockIdx.x * 256 + t;
    int v = (i < n) ? g_cnt[i] : 0;
    smv[t] = v;
    __syncthreads();
    #pragma unroll
    for (int off = 1; off < 256; off <<= 1) {
        int x = (t >= off) ? smv[t - off] : 0;
        __syncthreads();
        smv[t] += x;
        __syncthreads();
    }
    if (i < n) g_off[i] = smv[t] - v;
    if (t == 255) g_blk[blockIdx.x] = smv[255];
}
__global__ void scan2(int nb) {
    __shared__ int smv[256];
    int t = threadIdx.x;
    int v = (t < nb) ? g_blk[t] : 0;
    smv[t] = v;
    __syncthreads();
    #pragma unroll
    for (int off = 1; off < 256; off <<= 1) {
        int x = (t >= off) ? smv[t - off] : 0;
        __syncthreads();
        smv[t] += x;
        __syncthreads();
    }
    if (t < nb) g_blk[t] = smv[t] - v;
}
__global__ void scan3(int n) {
    int i = blockIdx.x * blockDim.x + threadIdx.x;
    if (i < n) {
        int o = g_off[i] + g_blk[i >> 8];
        g_off[i] = o;
        g_cur[i] = o;
    }
}
__global__ void fill_kernel(const int* __restrict__ ei, int E) {
    int e = blockIdx.x * blockDim.x + threadIdx.x;
    if (e < E) {
        int s = __ldg(ei + e);
        int d = __ldg(ei + E + e);
        int p = atomicAdd(&g_cur[d], 1);
        g_adj[p] = s;
    }
}

// -------------------- CSR aggregate: mean of h[src] per dst ------------------
template<int SRC>
__global__ void aggregate_kernel(int n) {
    int gw = (blockIdx.x * blockDim.x + threadIdx.x) >> 5;
    if (gw >= n) return;
    int lane = threadIdx.x & 31;
    const float* h = (SRC == 0) ? g_h0 : g_h1;
    int start = g_off[gw];
    int c = g_cnt[gw];
    float4 acc0 = make_float4(0.f, 0.f, 0.f, 0.f);
    float4 acc1 = make_float4(0.f, 0.f, 0.f, 0.f);
    int j = 0;
    for (; j + 2 <= c; j += 2) {
        int s0 = __ldg(g_adj + start + j);
        int s1 = __ldg(g_adj + start + j + 1);
        float4 v0 = __ldg((const float4*)(h + (size_t)s0 * H) + lane);
        float4 v1 = __ldg((const float4*)(h + (size_t)s1 * H) + lane);
        acc0.x += v0.x; acc0.y += v0.y; acc0.z += v0.z; acc0.w += v0.w;
        acc1.x += v1.x; acc1.y += v1.y; acc1.z += v1.z; acc1.w += v1.w;
    }
    if (j < c) {
        int s0 = __ldg(g_adj + start + j);
        float4 v0 = __ldg((const float4*)(h + (size_t)s0 * H) + lane);
        acc0.x += v0.x; acc0.y += v0.y; acc0.z += v0.z; acc0.w += v0.w;
    }
    float sc = (c > 0) ? (1.0f / (float)c) : 0.0f;
    float4 o;
    o.x = (acc0.x + acc1.x) * sc;
    o.y = (acc0.y + acc1.y) * sc;
    o.z = (acc0.z + acc1.z) * sc;
    o.w = (acc0.w + acc1.w) * sc;
    ((float4*)(g_agg + (size_t)gw * H))[lane] = o;
}

// smem layout (floats)
#define WROW      264                     // row-pair stride: 128 pairs (256) + 8 pad
#define SMF_W     0                       // 2 * 16*264 = 8448
#define SMF_A     8448                    // 2 * 128*32 = 8192
#define SMF_C     16640                   // 768
#define SMF_RS    17408                   // 512
#define SMF_RSS   17920                   // 512
#define SMF_MU    18432                   // 128
#define SMF_RSTD  18560                   // 128
#define SMF_KIND  18688                   // 128
#define SMF_TOTAL 18816
#define SM_BYTES  (SMF_TOTAL * 4)

// -------------------- pipelined tf32 mma GEMM + fused epilogue ---------------
// MODE 0: A=x[N,256], W=W_in            -> h0 = ..+b_in+kind_embed[k]+relay*ext
// MODE 1: A=[agg | h0], W=[Wl1;Wr1]     -> relu(LN(..+bl1)) -> h1
// MODE 2: A=[agg | h1], W=[Wl2;Wr2]     -> ..+bl2 -> out
template<int MODE>
__global__ void __launch_bounds__(TPB, 1)
tc_gemm(const float* __restrict__ Aext,
        const float* __restrict__ W0,
        const float* __restrict__ W1,
        const float* __restrict__ bias,
        const float* __restrict__ aux0,   // MODE0 kind_embed / MODE1 gamma
        const float* __restrict__ aux1,   // MODE0 ext_seed   / MODE1 beta
        const int*   __restrict__ node_kind,
        float* __restrict__ outExt,
        int n)
{
    extern __shared__ float sm[];
    float* Wbuf[2] = { sm + SMF_W, sm + SMF_W + 16 * WROW };
    float* Abuf[2] = { sm + SMF_A, sm + SMF_A + 128 * 32 };
    float* csh   = sm + SMF_C;
    float* rs    = sm + SMF_RS;
    float* rss   = sm + SMF_RSS;
    float* mus   = sm + SMF_MU;
    float* rstds = sm + SMF_RSTD;
    int*   kindsh = (int*)(sm + SMF_KIND);

    const int tid = threadIdx.x;
    const int wid = tid >> 5;
    const int lid = tid & 31;
    const int lq = lid >> 2;
    const int lr = lid & 3;
    const int wr = wid & 3;        // 4 row-blocks of 32
    const int cw = wid >> 2;       // 4 col-blocks of 32
    const int row0 = blockIdx.x << 7;

    // A staging roles
    const int arow = tid >> 2;     // 0..127
    const int ag   = tid & 3;      // k-group of 8
    const int agr  = row0 + arow;

    const float* Asrc = (MODE == 1) ? (const float*)g_h0 : (const float*)g_h1;

    float4 va, vb, wa, wb;

    auto ldgA = [&](int ch) {
        va = make_float4(0.f,0.f,0.f,0.f); vb = va;
        if (agr < n) {
            if (MODE == 0) {
                const float4* s = (const float4*)(Aext + (size_t)agr * KTOT + ch * 32 + ag * 8);
                va = __ldg(s); vb = __ldg(s + 1);
            } else if (ch < 4) {
                const float4* s = (const float4*)(g_agg + (size_t)agr * H + ch * 32 + ag * 8);
                va = __ldg(s); vb = __ldg(s + 1);
            } else {
                const float4* s = (const float4*)(Asrc + (size_t)agr * H + (ch - 4) * 32 + ag * 8);
                va = __ldg(s); vb = __ldg(s + 1);
            }
        }
    };
    auto stsA = [&](int ch, int p) {
        uint4 s0, s1;
        s0.x = tf32r(va.x); s0.y = tf32r(vb.x);
        s0.z = tf32r(va.y); s0.w = tf32r(vb.y);
        s1.x = tf32r(va.z); s1.y = tf32r(vb.z);
        s1.z = tf32r(va.w); s1.w = tf32r(vb.w);
        int u0 = (ag * 2) ^ ((arow & 3) << 1);
        uint4* d = (uint4*)&Abuf[p][arow * 32 + u0 * 4];
        d[0] = s0; d[1] = s1;
    };
    // W staging: warp wid stages k-row pair (k1 = ch*32 + (wid>>2)*8 + (wid&3), k2 = k1+4),
    // interleaved pairs, row stride WROW (conflict-free STS.128 + LDS.64)
    auto ldgW = [&](int ch) {
        int k1 = ch * 32 + ((wid >> 2) << 3) + (wid & 3);
        int k2 = k1 + 4;
        const float *r1, *r2;
        if (MODE == 0 || k1 < H) r1 = W0 + (size_t)k1 * H;
        else                     r1 = W1 + (size_t)(k1 - H) * H;
        if (MODE == 0 || k2 < H) r2 = W0 + (size_t)k2 * H;
        else                     r2 = W1 + (size_t)(k2 - H) * H;
        wa = __ldg((const float4*)r1 + lid);
        wb = __ldg((const float4*)r2 + lid);
    };
    auto stsW = [&](int p) {
        uint4 o0, o1;
        o0.x = tf32r(wa.x); o0.y = tf32r(wb.x); o0.z = tf32r(wa.y); o0.w = tf32r(wb.y);
        o1.x = tf32r(wa.z); o1.y = tf32r(wb.z); o1.z = tf32r(wa.w); o1.w = tf32r(wb.w);
        uint4* d = (uint4*)&Wbuf[p][wid * WROW + lid * 8];
        d[0] = o0; d[1] = o1;
    };

    // ---- prologue ----
    ldgA(0); ldgW(0);
    if (tid < H) csh[tid] = __ldg(bias + tid);
    if (MODE == 0) {
        if (tid >= H && tid < H + 3 * H) csh[tid] = __ldg(aux0 + (tid - H));
        if (tid < H) csh[4 * H + tid] = __ldg(aux1 + tid);
        if (tid < 128) kindsh[tid] = (row0 + tid < n) ? __ldg(node_kind + row0 + tid) : 0;
    } else if (MODE == 1) {
        if (tid < H) { csh[H + tid] = __ldg(aux0 + tid); csh[2 * H + tid] = __ldg(aux1 + tid); }
    }
    __syncthreads();
    stsA(0, 0); stsW(0);
    ldgA(1); ldgW(1);
    __syncthreads();

    float acc[2][4][4];
    #pragma unroll
    for (int mf = 0; mf < 2; mf++)
        #pragma unroll
        for (int nf = 0; nf < 4; nf++)
            #pragma unroll
            for (int q = 0; q < 4; q++) acc[mf][nf][q] = 0.f;

    int p = 0;
    #pragma unroll
    for (int ch = 0; ch < 8; ch++) {
        const float* Ab = Abuf[p];
        const float* Wb = Wbuf[p];
        #pragma unroll
        for (int ks = 0; ks < 4; ks++) {
            uint32_t a[2][4];
            #pragma unroll
            for (int mf = 0; mf < 2; mf++) {
                int rlo = wr * 32 + mf * 16 + lq;
                int u = (ks * 2 + (lr >> 1)) ^ ((lq & 3) << 1);
                float2 lo = *(const float2*)&Ab[rlo * 32 + u * 4 + (lr & 1) * 2];
                float2 hi = *(const float2*)&Ab[(rlo + 8) * 32 + u * 4 + (lr & 1) * 2];
                a[mf][0] = __float_as_uint(lo.x);
                a[mf][1] = __float_as_uint(hi.x);
                a[mf][2] = __float_as_uint(lo.y);
                a[mf][3] = __float_as_uint(hi.y);
            }
            uint32_t b[4][2];
            #pragma unroll
            for (int nf = 0; nf < 4; nf++) {
                float2 bv = *(const float2*)&Wb[(ks * 4 + lr) * WROW
                                                + (cw * 32 + nf * 8 + lq) * 2];
                b[nf][0] = __float_as_uint(bv.x);
                b[nf][1] = __float_as_uint(bv.y);
            }
            #pragma unroll
            for (int mf = 0; mf < 2; mf++)
                #pragma unroll
                for (int nf = 0; nf < 4; nf++)
                    mma_tf32(acc[mf][nf], a[mf], b[nf]);
        }
        if (ch < 7) {
            stsA(ch + 1, p ^ 1); stsW(p ^ 1);
            if (ch < 6) { ldgA(ch + 2); ldgW(ch + 2); }
        }
        __syncthreads();
        p ^= 1;
    }

    // ---------------- epilogue ----------------
    #pragma unroll
    for (int mf = 0; mf < 2; mf++)
        #pragma unroll
        for (int nf = 0; nf < 4; nf++) {
            int c0 = cw * 32 + nf * 8 + 2 * lr;
            float b0v = csh[c0], b1v = csh[c0 + 1];
            acc[mf][nf][0] += b0v; acc[mf][nf][1] += b1v;
            acc[mf][nf][2] += b0v; acc[mf][nf][3] += b1v;
        }

    if (MODE == 1) {
        #pragma unroll
        for (int mf = 0; mf < 2; mf++) {
            float slo = 0.f, sslo = 0.f, shi = 0.f, sshi = 0.f;
            #pragma unroll
            for (int nf = 0; nf < 4; nf++) {
                float v0 = acc[mf][nf][0], v1 = acc[mf][nf][1];
                float v2 = acc[mf][nf][2], v3 = acc[mf][nf][3];
                slo += v0 + v1;  sslo += v0 * v0 + v1 * v1;
                shi += v2 + v3;  sshi += v2 * v2 + v3 * v3;
            }
            #pragma unroll
            for (int m = 1; m <= 2; m <<= 1) {
                slo  += __shfl_xor_sync(0xffffffffu, slo,  m);
                sslo += __shfl_xor_sync(0xffffffffu, sslo, m);
                shi  += __shfl_xor_sync(0xffffffffu, shi,  m);
                sshi += __shfl_xor_sync(0xffffffffu, sshi, m);
            }
            if (lr == 0) {
                int rlo = wr * 32 + mf * 16 + lq;
                rs [rlo * 4 + cw] = slo;       rss[rlo * 4 + cw] = sslo;
                rs [(rlo + 8) * 4 + cw] = shi; rss[(rlo + 8) * 4 + cw] = sshi;
            }
        }
        __syncthreads();
        if (tid < 128) {
            float s  = rs [tid * 4] + rs [tid * 4 + 1] + rs [tid * 4 + 2] + rs [tid * 4 + 3];
            float ss = rss[tid * 4] + rss[tid * 4 + 1] + rss[tid * 4 + 2] + rss[tid * 4 + 3];
            float mu  = s * (1.0f / H);
            float var = ss * (1.0f / H) - mu * mu;
            mus[tid] = mu;
            rstds[tid] = rsqrtf(var + 1e-5f);
        }
        __syncthreads();
        #pragma unroll
        for (int mf = 0; mf < 2; mf++) {
            int lrow = wr * 32 + mf * 16 + lq;
            float mu_lo = mus[lrow],     rd_lo = rstds[lrow];
            float mu_hi = mus[lrow + 8], rd_hi = rstds[lrow + 8];
            int glo = row0 + lrow, ghi = glo + 8;
            #pragma unroll
            for (int nf = 0; nf < 4; nf++) {
                int c0 = cw * 32 + nf * 8 + 2 * lr;
                float g0 = csh[H + c0], g1 = csh[H + c0 + 1];
                float be0 = csh[2 * H + c0], be1 = csh[2 * H + c0 + 1];
                if (glo < n) {
                    float2 o;
                    o.x = fmaxf((acc[mf][nf][0] - mu_lo) * rd_lo * g0 + be0, 0.f);
                    o.y = fmaxf((acc[mf][nf][1] - mu_lo) * rd_lo * g1 + be1, 0.f);
                    *(float2*)(g_h1 + (size_t)glo * H + c0) = o;
                }
                if (ghi < n) {
                    float2 o;
                    o.x = fmaxf((acc[mf][nf][2] - mu_hi) * rd_hi * g0 + be0, 0.f);
                    o.y = fmaxf((acc[mf][nf][3] - mu_hi) * rd_hi * g1 + be1, 0.f);
                    *(float2*)(g_h1 + (size_t)ghi * H + c0) = o;
                }
            }
        }
    } else {
        #pragma unroll
        for (int mf = 0; mf < 2; mf++) {
            int lrow = wr * 32 + mf * 16 + lq;
            int glo = row0 + lrow, ghi = glo + 8;
            int klo = 0, khi = 0;
            bool rlo = false, rhi = false;
            if (MODE == 0) {
                klo = kindsh[lrow]; khi = kindsh[lrow + 8];
                rlo = (klo != 0);   rhi = (khi != 0);
            }
            float* dst = (MODE == 0) ? g_h0 : outExt;
            #pragma unroll
            for (int nf = 0; nf < 4; nf++) {
                int c0 = cw * 32 + nf * 8 + 2 * lr;
                if (glo < n) {
                    float2 o = make_float2(acc[mf][nf][0], acc[mf][nf][1]);
                    if (MODE == 0) {
                        o.x += csh[H + klo * H + c0];
                        o.y += csh[H + klo * H + c0 + 1];
                        if (rlo) { o.x += csh[4 * H + c0]; o.y += csh[4 * H + c0 + 1]; }
                    }
                    *(float2*)(dst + (size_t)glo * H + c0) = o;
                }
                if (ghi < n) {
                    float2 o = make_float2(acc[mf][nf][2], acc[mf][nf][3]);
                    if (MODE == 0) {
                        o.x += csh[H + khi * H + c0];
                        o.y += csh[H + khi * H + c0 + 1];
                        if (rhi) { o.x += csh[4 * H + c0]; o.y += csh[4 * H + c0 + 1]; }
                    }
                    *(float2*)(dst + (size_t)ghi * H + c0) = o;
                }
            }
        }
    }
}

// ---------------------------------------------------------------------------
extern "C" void kernel_launch(void* const* d_in, const int* in_sizes, int n_in,
                              void* d_out, int out_size) {
    const float* x          = (const float*)d_in[0];
    const int*   ei         = (const int*)d_in[1];
    const int*   node_kind  = (const int*)d_in[2];
    const float* W_in       = (const float*)d_in[3];
    const float* b_in       = (const float*)d_in[4];
    const float* kind_embed = (const float*)d_in[5];
    const float* ext_seed   = (const float*)d_in[6];
    const float* Wl1        = (const float*)d_in[7];
    const float* bl1        = (const float*)d_in[8];
    const float* Wr1        = (const float*)d_in[9];
    const float* gamma      = (const float*)d_in[10];
    const float* beta       = (const float*)d_in[11];
    const float* Wl2        = (const float*)d_in[12];
    const float* bl2        = (const float*)d_in[13];
    const float* Wr2        = (const float*)d_in[14];

    int n = in_sizes[2];
    int E = in_sizes[1] / 2;

    cudaFuncSetAttribute(tc_gemm<0>, cudaFuncAttributeMaxDynamicSharedMemorySize, SM_BYTES);
    cudaFuncSetAttribute(tc_gemm<1>, cudaFuncAttributeMaxDynamicSharedMemorySize, SM_BYTES);
    cudaFuncSetAttribute(tc_gemm<2>, cudaFuncAttributeMaxDynamicSharedMemorySize, SM_BYTES);

    int ntiles = (n + 127) / 128;
    int nb256  = (n + 255) / 256;
    int eb256  = (E + 255) / 256;
    int aggblk = (n * 32 + 255) / 256;

    // ---- fork: CSR build on side stream, concurrent with gemm0 ----
    cudaStream_t s2;
    cudaStreamCreateWithFlags(&s2, cudaStreamNonBlocking);
    cudaEvent_t e1, e2;
    cudaEventCreateWithFlags(&e1, cudaEventDisableTiming);
    cudaEventCreateWithFlags(&e2, cudaEventDisableTiming);

    cudaEventRecord(e1, 0);
    cudaStreamWaitEvent(s2, e1, 0);
    zero_cnt<<<nb256, 256, 0, s2>>>(n);
    hist_kernel<<<eb256, 256, 0, s2>>>(ei, E);
    scan1<<<nb256, 256, 0, s2>>>(n);
    scan2<<<1, 256, 0, s2>>>(nb256);
    scan3<<<nb256, 256, 0, s2>>>(n);
    fill_kernel<<<eb256, 256, 0, s2>>>(ei, E);
    cudaEventRecord(e2, s2);

    // gemm0 on main stream, overlapping the CSR chain
    tc_gemm<0><<<ntiles, TPB, SM_BYTES>>>(x, W_in, nullptr, b_in, kind_embed,
                                          ext_seed, node_kind, nullptr, n);

    // ---- join: aggregate needs both h0 and CSR ----
    cudaStreamWaitEvent(0, e2, 0);
    aggregate_kernel<0><<<aggblk, 256>>>(n);
    tc_gemm<1><<<ntiles, TPB, SM_BYTES>>>(nullptr, Wl1, Wr1, bl1, gamma, beta,
                                          nullptr, nullptr, n);
    aggregate_kernel<1><<<aggblk, 256>>>(n);
    tc_gemm<2><<<ntiles, TPB, SM_BYTES>>>(nullptr, Wl2, Wr2, bl2, nullptr, nullptr,
                                          nullptr, (float*)d_out, n);
}